// round 16
// baseline (speedup 1.0000x reference)
#include <cuda_runtime.h>
#include <cuda_bf16.h>
#include <math.h>
#include <cstdint>

// Shapes fixed by the problem
#define NN     1024
#define LL     30
#define GG     10000
#define NBATCH 64
#define NT     256     // threads per block
#define GT     256     // genes per block (2 per lane-pair)
#define GH     128     // gene stride between a pair's two genes

typedef unsigned long long u64;

// Device scratch (allocation-free rule: __device__ globals)
__device__ __align__(16) float g_zperm[NN * 32];  // batch-sorted z, padded to 32
__device__ float g_sfperm[NN];
__device__ int   g_cellid[NN];
__device__ int   g_bstart[NBATCH + 1];

// ---- packed f32x2 helpers (sm_103a) ---------------------------------------
#define FMA2(d, a, b, c) \
    asm("fma.rn.f32x2 %0, %1, %2, %3;" : "=l"(d) : "l"(a), "l"(b), "l"(c))
#define ADD2(d, a, b) \
    asm("add.rn.f32x2 %0, %1, %2;" : "=l"(d) : "l"(a), "l"(b))
#define PACK2(d, lo, hi) \
    asm("mov.b64 %0, {%1, %2};" : "=l"(d) : "f"(lo), "f"(hi))
#define UNPACK2(lo, hi, s) \
    asm("mov.b64 {%0, %1}, %2;" : "=f"(lo), "=f"(hi) : "l"(s))

__device__ __forceinline__ float softplus_fast(float x) {
    return fmaxf(x, 0.f) + __logf(1.f + __expf(-fabsf(x)));
}

// ---------------------------------------------------------------------------
// Kernel 1: prep. Blocks 0..39: exp(px_r) tail. Block 40: counting-sort of
// cells by batch + materialize zperm (padded rows), sfperm, cellid, bstart.
// ---------------------------------------------------------------------------
__global__ void prep_kernel(const int* __restrict__ bc,
                            const float* __restrict__ z,
                            const float* __restrict__ sf,
                            const float* __restrict__ px_r,
                            float* __restrict__ out) {
    if (blockIdx.x < 40) {
        int i = blockIdx.x * 256 + threadIdx.x;
        if (i < GG) out[(size_t)NN * GG + i] = __expf(px_r[i]);
        return;
    }
    __shared__ int cnt[NBATCH];
    __shared__ int start[NBATCH + 1];
    __shared__ int cur[NBATCH];
    int t = threadIdx.x;
    if (t < NBATCH) cnt[t] = 0;
    __syncthreads();
    int myb[4];
#pragma unroll
    for (int q = 0; q < 4; q++) {
        myb[q] = bc[t + q * 256];
        atomicAdd(&cnt[myb[q]], 1);
    }
    __syncthreads();
    if (t == 0) {
        int s = 0;
        for (int i = 0; i < NBATCH; i++) { start[i] = s; s += cnt[i]; }
        start[NBATCH] = s;
    }
    __syncthreads();
    if (t < NBATCH) cur[t] = start[t];
    __syncthreads();
#pragma unroll
    for (int q = 0; q < 4; q++) {
        int c = t + q * 256;
        int p = atomicAdd(&cur[myb[q]], 1);
        g_cellid[p] = c;
        g_sfperm[p] = sf[c];
#pragma unroll
        for (int l = 0; l < LL; l++) g_zperm[p * 32 + l] = z[c * LL + l];
        g_zperm[p * 32 + 30] = 0.f;
        g_zperm[p * 32 + 31] = 0.f;
    }
    if (t <= NBATCH) g_bstart[t] = start[t];
}

// ---------------------------------------------------------------------------
// Kernel 2: barrier-free, smem-free decoder. Grid = (40, 64), 256 threads.
// Lane pair (2t, 2t+1): even lane holds K 0..15, odd K 16..31 of genes
// gA = g0 + (tid>>1), gB = gA + 128. Per cell: 4 LDG.128 of L1-hot zperm +
// 16 FMA2 (2 genes, 2 chains) + ONE shfl exchange -> each lane emits one
// softplus+STG. 2-cell interleave for ILP. A is read with __ldcs and out
// written with __stcs so they stream past L1, keeping zperm resident.
// No __syncthreads anywhere: warps are fully independent.
// ---------------------------------------------------------------------------
__global__ __launch_bounds__(NT, 4)
void decoder_kernel(const float* __restrict__ W,
                    const float* __restrict__ A,
                    const float* __restrict__ bemb,
                    float* __restrict__ out) {
    const int tid = threadIdx.x;
    const int h   = tid & 1;          // K-half selector
    const int gl  = tid >> 1;
    const int b   = blockIdx.y;
    const int g0  = blockIdx.x * GT;

    const int gA  = g0 + gl;
    const int gB  = gA + GH;
    const int myg = h ? gB : gA;      // gene this lane emits

    // Fold this lane's K-half of C = A[b,g,:] + W[:,g] for both genes.
    // A is touch-once -> __ldcs (evict-first) to protect zperm in L1.
    u64 CA[8], CB[8];
    const int k0 = h * 16;
    const int np = h ? 7 : 8;         // odd half: 7 real pairs + zero pad
    if (gA < GG) {
        const u64* Ar = (const u64*)(A + ((size_t)b * GG + gA) * LL) + h * 8;
#pragma unroll
        for (int q = 0; q < 8; q++) {
            if (q < np) {
                u64 w2;
                PACK2(w2, W[(k0 + 2 * q) * GG + gA], W[(k0 + 2 * q + 1) * GG + gA]);
                ADD2(CA[q], __ldcs(Ar + q), w2);
            } else CA[q] = 0ULL;
        }
    } else {
#pragma unroll
        for (int q = 0; q < 8; q++) CA[q] = 0ULL;
    }
    if (gB < GG) {
        const u64* Ar = (const u64*)(A + ((size_t)b * GG + gB) * LL) + h * 8;
#pragma unroll
        for (int q = 0; q < 8; q++) {
            if (q < np) {
                u64 w2;
                PACK2(w2, W[(k0 + 2 * q) * GG + gB], W[(k0 + 2 * q + 1) * GG + gB]);
                ADD2(CB[q], __ldcs(Ar + q), w2);
            } else CB[q] = 0ULL;
        }
    } else {
#pragma unroll
        for (int q = 0; q < 8; q++) CB[q] = 0ULL;
    }
    const float mybb = (myg < GG) ? bemb[(size_t)b * GG + myg] : 0.f;
    const bool  emit = (myg < GG);

    const int s = g_bstart[b];
    const int e = g_bstart[b + 1];

    int j = s;
    // ---- 2-cell interleaved main loop ------------------------------------
    for (; j + 2 <= e; j += 2) {
        const ulonglong2* zp0 = (const ulonglong2*)(g_zperm + (size_t)j * 32 + h * 16);
        const ulonglong2* zp1 = (const ulonglong2*)(g_zperm + (size_t)(j + 1) * 32 + h * 16);
        ulonglong2 p0 = zp0[0], p1 = zp0[1], p2 = zp0[2], p3 = zp0[3];
        ulonglong2 q0 = zp1[0], q1 = zp1[1], q2 = zp1[2], q3 = zp1[3];

        u64 aA0 = 0ULL, aB0 = 0ULL, aA1 = 0ULL, aB1 = 0ULL;
        FMA2(aA0, CA[0], p0.x, aA0);  FMA2(aA1, CA[0], q0.x, aA1);
        FMA2(aB0, CB[0], p0.x, aB0);  FMA2(aB1, CB[0], q0.x, aB1);
        FMA2(aA0, CA[1], p0.y, aA0);  FMA2(aA1, CA[1], q0.y, aA1);
        FMA2(aB0, CB[1], p0.y, aB0);  FMA2(aB1, CB[1], q0.y, aB1);
        FMA2(aA0, CA[2], p1.x, aA0);  FMA2(aA1, CA[2], q1.x, aA1);
        FMA2(aB0, CB[2], p1.x, aB0);  FMA2(aB1, CB[2], q1.x, aB1);
        FMA2(aA0, CA[3], p1.y, aA0);  FMA2(aA1, CA[3], q1.y, aA1);
        FMA2(aB0, CB[3], p1.y, aB0);  FMA2(aB1, CB[3], q1.y, aB1);
        FMA2(aA0, CA[4], p2.x, aA0);  FMA2(aA1, CA[4], q2.x, aA1);
        FMA2(aB0, CB[4], p2.x, aB0);  FMA2(aB1, CB[4], q2.x, aB1);
        FMA2(aA0, CA[5], p2.y, aA0);  FMA2(aA1, CA[5], q2.y, aA1);
        FMA2(aB0, CB[5], p2.y, aB0);  FMA2(aB1, CB[5], q2.y, aB1);
        FMA2(aA0, CA[6], p3.x, aA0);  FMA2(aA1, CA[6], q3.x, aA1);
        FMA2(aB0, CB[6], p3.x, aB0);  FMA2(aB1, CB[6], q3.x, aB1);
        FMA2(aA0, CA[7], p3.y, aA0);  FMA2(aA1, CA[7], q3.y, aA1);
        FMA2(aB0, CB[7], p3.y, aB0);  FMA2(aB1, CB[7], q3.y, aB1);

        float xA, yA, xB, yB;
        UNPACK2(xA, yA, aA0);  UNPACK2(xB, yB, aB0);
        float fA0 = xA + yA, fB0 = xB + yB;
        UNPACK2(xA, yA, aA1);  UNPACK2(xB, yB, aB1);
        float fA1 = xA + yA, fB1 = xB + yB;

        // single exchange per cell: send what the partner's gene needs
        float keep0 = h ? fB0 : fA0, send0 = h ? fA0 : fB0;
        float keep1 = h ? fB1 : fA1, send1 = h ? fA1 : fB1;
        float recv0 = __shfl_xor_sync(0xffffffffu, send0, 1);
        float recv1 = __shfl_xor_sync(0xffffffffu, send1, 1);

        if (emit) {
            float acc0 = keep0 + recv0 + mybb;
            float acc1 = keep1 + recv1 + mybb;
            float r0 = softplus_fast(acc0) * g_sfperm[j];
            float r1 = softplus_fast(acc1) * g_sfperm[j + 1];
            __stcs(&out[(size_t)g_cellid[j]     * GG + myg], r0);
            __stcs(&out[(size_t)g_cellid[j + 1] * GG + myg], r1);
        }
    }
    // ---- tail (single cell) ----------------------------------------------
    for (; j < e; j++) {
        const ulonglong2* zp = (const ulonglong2*)(g_zperm + (size_t)j * 32 + h * 16);
        ulonglong2 v0 = zp[0], v1 = zp[1], v2 = zp[2], v3 = zp[3];
        u64 aA = 0ULL, aB = 0ULL;
        FMA2(aA, CA[0], v0.x, aA);  FMA2(aB, CB[0], v0.x, aB);
        FMA2(aA, CA[1], v0.y, aA);  FMA2(aB, CB[1], v0.y, aB);
        FMA2(aA, CA[2], v1.x, aA);  FMA2(aB, CB[2], v1.x, aB);
        FMA2(aA, CA[3], v1.y, aA);  FMA2(aB, CB[3], v1.y, aB);
        FMA2(aA, CA[4], v2.x, aA);  FMA2(aB, CB[4], v2.x, aB);
        FMA2(aA, CA[5], v2.y, aA);  FMA2(aB, CB[5], v2.y, aB);
        FMA2(aA, CA[6], v3.x, aA);  FMA2(aB, CB[6], v3.x, aB);
        FMA2(aA, CA[7], v3.y, aA);  FMA2(aB, CB[7], v3.y, aB);

        float xA, yA, xB, yB;
        UNPACK2(xA, yA, aA);  UNPACK2(xB, yB, aB);
        float fA = xA + yA, fB = xB + yB;
        float keep = h ? fB : fA, send = h ? fA : fB;
        float recv = __shfl_xor_sync(0xffffffffu, send, 1);
        if (emit) {
            float acc = keep + recv + mybb;
            float r = softplus_fast(acc) * g_sfperm[j];
            __stcs(&out[(size_t)g_cellid[j] * GG + myg], r);
        }
    }
}

// ---------------------------------------------------------------------------
// Launch. Inputs per metadata order:
//   0: z [N,L] f32        1: batch_covariate [N] i32   2: size_factor [N,1] f32
//   3: W_amat [L,G] f32   4: A_emb [NB,G,L] f32        5: b_emb [NB,G] f32
//   6: px_r [G] f32
// Output: mean [N,G] f32 followed by inverse_dispersion [G] f32.
// ---------------------------------------------------------------------------
extern "C" void kernel_launch(void* const* d_in, const int* in_sizes, int n_in,
                              void* d_out, int out_size) {
    const float* z    = (const float*)d_in[0];
    const int*   bc   = (const int*)  d_in[1];
    const float* sf   = (const float*)d_in[2];
    const float* W    = (const float*)d_in[3];
    const float* A    = (const float*)d_in[4];
    const float* bemb = (const float*)d_in[5];
    const float* pxr  = (const float*)d_in[6];
    float* out = (float*)d_out;

    prep_kernel<<<41, 256>>>(bc, z, sf, pxr, out);

    dim3 grid((GG + GT - 1) / GT, NBATCH);
    decoder_kernel<<<grid, NT>>>(W, A, bemb, out);
}